// round 16
// baseline (speedup 1.0000x reference)
#include <cuda_runtime.h>
#include <cuda_fp16.h>
#include <cstdint>

#define N_NODES 20000
#define N_EDGES 160000
#define N_IN    512
#define N_OUT   512
#define M_PAD   20096            // 157 * 128

// Static device scratch (no runtime allocation; zero-initialized at load)
__device__ __half         g_Ahi[(size_t)M_PAD * N_IN];   // 20.6 MB (padding rows stay 0)
__device__ __half         g_x16[(size_t)N_NODES * N_IN]; // 20.5 MB fp16 copy of x
__device__ __half         g_Whi[(size_t)N_OUT * N_IN];   // 0.5 MB
__device__ int            g_cnt[N_NODES];                // histogram, then fill cursor
__device__ int            g_ofs[N_NODES + 1];            // CSR row offsets
__device__ int            g_csr_col[N_EDGES];
__device__ float          g_csr_val[N_EDGES];

// ---------------------------------------------------------------------------
// Helpers
// ---------------------------------------------------------------------------
__device__ __forceinline__ uint32_t smem_u32(const void* p) {
    uint32_t a;
    asm("{ .reg .u64 t; cvta.to.shared.u64 t, %1; cvt.u32.u64 %0, t; }"
        : "=r"(a) : "l"(p));
    return a;
}

__device__ __forceinline__ void cp_async16(uint32_t smem_addr, const void* gptr) {
    asm volatile("cp.async.cg.shared.global [%0], [%1], 16;"
                 :: "r"(smem_addr), "l"(gptr) : "memory");
}

__device__ __forceinline__ void ldsm_x4(uint32_t& r0, uint32_t& r1,
                                        uint32_t& r2, uint32_t& r3, uint32_t addr) {
    asm volatile("ldmatrix.sync.aligned.m8n8.x4.shared.b16 {%0,%1,%2,%3}, [%4];"
                 : "=r"(r0), "=r"(r1), "=r"(r2), "=r"(r3) : "r"(addr));
}

__device__ __forceinline__ void mma_f16(float& c0, float& c1, float& c2, float& c3,
                                        uint32_t a0, uint32_t a1, uint32_t a2, uint32_t a3,
                                        uint32_t b0, uint32_t b1) {
    asm volatile(
        "mma.sync.aligned.m16n8k16.row.col.f32.f16.f16.f32 "
        "{%0,%1,%2,%3}, {%4,%5,%6,%7}, {%8,%9}, {%0,%1,%2,%3};"
        : "+f"(c0), "+f"(c1), "+f"(c2), "+f"(c3)
        : "r"(a0), "r"(a1), "r"(a2), "r"(a3), "r"(b0), "r"(b1));
}

// SW128 swizzle for 128-byte rows
__device__ __forceinline__ uint32_t sw128(uint32_t off) {
    return off ^ ((off >> 3) & 0x70);
}

// ---------------------------------------------------------------------------
// x -> fp16 pre-convert (halves gather L2 traffic)
// ---------------------------------------------------------------------------
__global__ void convert_x_kernel(const float* __restrict__ x) {
    const int n4 = (N_NODES * N_IN) / 4;
    const float4* src = reinterpret_cast<const float4*>(x);
    uint2* dst = reinterpret_cast<uint2*>(g_x16);
    for (int i = blockIdx.x * blockDim.x + threadIdx.x; i < n4;
         i += gridDim.x * blockDim.x) {
        float4 f = src[i];
        __half2 H0 = __halves2half2(__float2half_rn(f.x), __float2half_rn(f.y));
        __half2 H1 = __halves2half2(__float2half_rn(f.z), __float2half_rn(f.w));
        dst[i] = make_uint2(*reinterpret_cast<uint32_t*>(&H0),
                            *reinterpret_cast<uint32_t*>(&H1));
    }
}

// ---------------------------------------------------------------------------
// CSR build: zero counts -> histogram -> scan -> fill
// ---------------------------------------------------------------------------
__global__ void zero_cnt_kernel() {
    int i = blockIdx.x * blockDim.x + threadIdx.x;
    if (i < N_NODES) g_cnt[i] = 0;
}

__global__ void hist_kernel(const int* __restrict__ row, int E) {
    int e = blockIdx.x * blockDim.x + threadIdx.x;
    if (e < E) atomicAdd(&g_cnt[row[e]], 1);
}

// Single-block exclusive scan of g_cnt -> g_ofs; re-init g_cnt as fill cursor.
__global__ __launch_bounds__(1024) void scan_kernel() {
    __shared__ int s[1024];
    const int t = threadIdx.x;
    const int PER = 20;                        // 1024*20 = 20480 >= N_NODES
    const int beg = t * PER;
    const int end = min(beg + PER, N_NODES);

    int part = 0;
    for (int i = beg; i < end; i++) part += g_cnt[i];
    s[t] = part;
    __syncthreads();
    for (int off = 1; off < 1024; off <<= 1) {
        int v = (t >= off) ? s[t - off] : 0;
        __syncthreads();
        s[t] += v;
        __syncthreads();
    }
    int base = s[t] - part;                    // exclusive prefix
    for (int i = beg; i < end; i++) {
        int c = g_cnt[i];
        g_ofs[i] = base;
        g_cnt[i] = base;                       // cursor for fill
        base += c;
    }
    if (t == 1023) g_ofs[N_NODES] = base;      // == E (tail parts are 0)
}

__global__ void fill_kernel(const float* __restrict__ vals,
                            const int* __restrict__ row,
                            const int* __restrict__ col, int E) {
    int e = blockIdx.x * blockDim.x + threadIdx.x;
    if (e < E) {
        int p = atomicAdd(&g_cnt[row[e]], 1);
        g_csr_col[p] = col[e];
        g_csr_val[p] = vals[e];
    }
}

// ---------------------------------------------------------------------------
// Gather (fp16 x, fp32 accum) + fp16 convert of the result row.
// One node per 128 threads (4 nodes / 512-thread block).
// ---------------------------------------------------------------------------
__global__ __launch_bounds__(512) void gather_split_kernel()
{
    const int node = blockIdx.x * 4 + (threadIdx.x >> 7);
    if (node >= N_NODES) return;
    const int f4 = threadIdx.x & 127;

    const int beg = g_ofs[node];
    const int end = g_ofs[node + 1];

    float4 acc = make_float4(0.f, 0.f, 0.f, 0.f);
    for (int p = beg; p < end; p++) {
        const int   c = g_csr_col[p];          // warp-uniform (broadcast)
        const float v = g_csr_val[p];
        uint2 xv = reinterpret_cast<const uint2*>(g_x16 + (size_t)c * N_IN)[f4];
        float2 f0 = __half22float2(*reinterpret_cast<__half2*>(&xv.x));
        float2 f1 = __half22float2(*reinterpret_cast<__half2*>(&xv.y));
        acc.x += v * f0.x; acc.y += v * f0.y;
        acc.z += v * f1.x; acc.w += v * f1.y;
    }

    __half2 H0 = __halves2half2(__float2half_rn(acc.x), __float2half_rn(acc.y));
    __half2 H1 = __halves2half2(__float2half_rn(acc.z), __float2half_rn(acc.w));
    uint2* hp = reinterpret_cast<uint2*>(g_Ahi + (size_t)node * N_IN) + f4;
    *hp = make_uint2(*reinterpret_cast<uint32_t*>(&H0),
                     *reinterpret_cast<uint32_t*>(&H1));
}

// ---------------------------------------------------------------------------
// W convert to fp16
// ---------------------------------------------------------------------------
__global__ void split_w_kernel(const float* __restrict__ W) {
    const int n4 = (N_OUT * N_IN) / 4;
    uint32_t* hi = reinterpret_cast<uint32_t*>(g_Whi);
    const float4* src = reinterpret_cast<const float4*>(W);
    for (int i = blockIdx.x * blockDim.x + threadIdx.x; i < n4;
         i += gridDim.x * blockDim.x) {
        float4 f = src[i];
        __half2 H0 = __halves2half2(__float2half_rn(f.x), __float2half_rn(f.y));
        __half2 H1 = __halves2half2(__float2half_rn(f.z), __float2half_rn(f.w));
        hi[i * 2]     = *reinterpret_cast<uint32_t*>(&H0);
        hi[i * 2 + 1] = *reinterpret_cast<uint32_t*>(&H1);
    }
}

// ---------------------------------------------------------------------------
// GEMM: out = agg @ W^T via mma.sync fp16, single chain, fp32 accum.
// Block tile 128x128, K=64 stages (2 tiles x 16 KB = 32 KB/stage),
// THREE stages (96 KB) -> 2 CTAs/SM, ONE __syncthreads per K-step:
//   iter s: wait group s; sync (also proves compute(s-1) done everywhere);
//   issue load(s+2) into stage (s+2)%3 == (s-1)%3; compute stage s%3.
// ---------------------------------------------------------------------------
#define GBM 128
#define GBN 128
#define NSTEP (N_IN / 64)      // 8 K-steps of 64

#define T_AHI 0
#define T_BHI 16384
#define STAGE_SZ 32768
#define GEMM_SMEM (3 * STAGE_SZ)   // 96 KB

__global__ __launch_bounds__(256, 2) void mma_gemm_kernel(float* __restrict__ out)
{
    extern __shared__ __align__(1024) char smem[];
    const uint32_t sbase = smem_u32(smem);
    const int tid = threadIdx.x;
    const int wid = tid >> 5;
    const int lane = tid & 31;
    const int wm = wid >> 2;            // 0..1 : rows wm*64
    const int wn = wid & 3;             // 0..3 : cols wn*32
    const int m0 = blockIdx.y * GBM;
    const int n0 = blockIdx.x * GBN;

    const int r = tid >> 1;             // 0..127 (tile row this thread loads)
    const int h = tid & 1;              // 0..1   (which 64B half of the 128B row)
    const char* srcA = (const char*)(g_Ahi + (size_t)(m0 + r) * N_IN);
    const char* srcB = (const char*)(g_Whi + (size_t)(n0 + r) * N_IN);

    // Load one K64 step (2 tiles x 128 rows x 128B) into a stage; commit group.
    auto load_step = [&](int step, uint32_t stg) {
        const int cbyte = step * 128;                // 64 fp16 = 128B per row
        #pragma unroll
        for (int jj = 0; jj < 4; jj++) {
            const int j = h * 4 + jj;                // 16B chunk 0..7
            const uint32_t dst = sw128((uint32_t)(r * 128 + j * 16));
            const int so = cbyte + j * 16;
            cp_async16(sbase + stg + T_AHI + dst, srcA + so);
            cp_async16(sbase + stg + T_BHI + dst, srcB + so);
        }
        asm volatile("cp.async.commit_group;" ::: "memory");
    };

    float acc[4][4][4];
    #pragma unroll
    for (int i = 0; i < 4; i++)
        #pragma unroll
        for (int j = 0; j < 4; j++)
            #pragma unroll
            for (int k = 0; k < 4; k++) acc[i][j][k] = 0.f;

    // Prologue: stages 0 and 1 in flight.
    load_step(0, 0);
    load_step(1, STAGE_SZ);

    for (int s = 0; s < NSTEP; s++) {
        const uint32_t stg = (uint32_t)(s % 3) * STAGE_SZ;

        // Wait until at most 1 group pending -> group s complete.
        asm volatile("cp.async.wait_group 1;" ::: "memory");
        __syncthreads();   // data(s) visible; all warps done computing s-1

        if (s + 2 < NSTEP)
            load_step(s + 2, (uint32_t)((s + 2) % 3) * STAGE_SZ);

        #pragma unroll
        for (int ks = 0; ks < 4; ks++) {     // four K16 sub-steps per stage
            uint32_t a[4][4], bh[4][2];

            // A fragments
            #pragma unroll
            for (int mf = 0; mf < 4; mf++) {
                uint32_t off = (uint32_t)((wm * 64 + mf * 16 +
                               ((lane >> 3) & 1) * 8 + (lane & 7)) * 128
                               + ks * 32 + (lane >> 4) * 16);
                ldsm_x4(a[mf][0], a[mf][1], a[mf][2], a[mf][3],
                        sbase + stg + T_AHI + sw128(off));
            }
            // B fragments
            #pragma unroll
            for (int nf2 = 0; nf2 < 2; nf2++) {
                uint32_t off = (uint32_t)((wn * 32 + nf2 * 16 +
                               ((lane >> 4) & 1) * 8 + (lane & 7)) * 128
                               + ks * 32 + ((lane >> 3) & 1) * 16);
                ldsm_x4(bh[nf2 * 2][0], bh[nf2 * 2][1],
                        bh[nf2 * 2 + 1][0], bh[nf2 * 2 + 1][1],
                        sbase + stg + T_BHI + sw128(off));
            }
            #pragma unroll
            for (int mf = 0; mf < 4; mf++)
                #pragma unroll
                for (int nf = 0; nf < 4; nf++)
                    mma_f16(acc[mf][nf][0], acc[mf][nf][1],
                            acc[mf][nf][2], acc[mf][nf][3],
                            a[mf][0], a[mf][1], a[mf][2], a[mf][3],
                            bh[nf][0], bh[nf][1]);
        }
    }

    // ---- epilogue (no smem use; no final sync needed) ----
    #pragma unroll
    for (int mf = 0; mf < 4; mf++) {
        const int mrow = m0 + wm * 64 + mf * 16 + (lane >> 2);
        #pragma unroll
        for (int nf = 0; nf < 4; nf++) {
            const int ncol = n0 + wn * 32 + nf * 8 + (lane & 3) * 2;
            if (mrow < N_NODES) {
                float2* p = reinterpret_cast<float2*>(out + (size_t)mrow * N_OUT + ncol);
                *p = make_float2(acc[mf][nf][0], acc[mf][nf][1]);
            }
            if (mrow + 8 < N_NODES) {
                float2* p = reinterpret_cast<float2*>(out + (size_t)(mrow + 8) * N_OUT + ncol);
                *p = make_float2(acc[mf][nf][2], acc[mf][nf][3]);
            }
        }
    }
}

// ---------------------------------------------------------------------------
// Launch
// ---------------------------------------------------------------------------
extern "C" void kernel_launch(void* const* d_in, const int* in_sizes, int n_in,
                              void* d_out, int out_size)
{
    const float* x    = (const float*)d_in[0];
    const float* vals = (const float*)d_in[1];
    const float* W    = (const float*)d_in[2];
    const int*   row  = (const int*)d_in[3];
    const int*   col  = (const int*)d_in[4];
    float*       out  = (float*)d_out;

    int E = in_sizes[1];

    static bool s_init = false;
    if (!s_init) {
        cudaFuncSetAttribute(mma_gemm_kernel,
                             cudaFuncAttributeMaxDynamicSharedMemorySize, GEMM_SMEM);
        s_init = true;
    }

    zero_cnt_kernel<<<(N_NODES + 511) / 512, 512>>>();
    hist_kernel<<<(E + 511) / 512, 512>>>(row, E);
    scan_kernel<<<1, 1024>>>();
    fill_kernel<<<(E + 511) / 512, 512>>>(vals, row, col, E);
    convert_x_kernel<<<2048, 256>>>(x);
    gather_split_kernel<<<(N_NODES + 3) / 4, 512>>>();
    split_w_kernel<<<256, 256>>>(W);

    dim3 grid(N_OUT / GBN, M_PAD / GBM);   // (4, 157)
    mma_gemm_kernel<<<grid, 256, GEMM_SMEM>>>(out);
}

// round 17
// speedup vs baseline: 1.0702x; 1.0702x over previous
#include <cuda_runtime.h>
#include <cuda_fp16.h>
#include <cstdint>

#define N_NODES 20000
#define N_EDGES 160000
#define N_IN    512
#define N_OUT   512
#define M_PAD   20096            // 157 * 128

// Static device scratch (no runtime allocation; zero-initialized at load)
__device__ __half         g_Ahi[(size_t)M_PAD * N_IN];   // 20.6 MB (padding rows stay 0)
__device__ __half         g_Whi[(size_t)N_OUT * N_IN];   // 0.5 MB
__device__ int            g_cnt[N_NODES];                // histogram, then fill cursor
__device__ int            g_ofs[N_NODES + 1];            // CSR row offsets
__device__ int            g_csr_col[N_EDGES];
__device__ float          g_csr_val[N_EDGES];

// ---------------------------------------------------------------------------
// Helpers
// ---------------------------------------------------------------------------
__device__ __forceinline__ uint32_t smem_u32(const void* p) {
    uint32_t a;
    asm("{ .reg .u64 t; cvta.to.shared.u64 t, %1; cvt.u32.u64 %0, t; }"
        : "=r"(a) : "l"(p));
    return a;
}

__device__ __forceinline__ void cp_async16(uint32_t smem_addr, const void* gptr) {
    asm volatile("cp.async.cg.shared.global [%0], [%1], 16;"
                 :: "r"(smem_addr), "l"(gptr) : "memory");
}

__device__ __forceinline__ void ldsm_x4(uint32_t& r0, uint32_t& r1,
                                        uint32_t& r2, uint32_t& r3, uint32_t addr) {
    asm volatile("ldmatrix.sync.aligned.m8n8.x4.shared.b16 {%0,%1,%2,%3}, [%4];"
                 : "=r"(r0), "=r"(r1), "=r"(r2), "=r"(r3) : "r"(addr));
}

__device__ __forceinline__ void mma_f16(float& c0, float& c1, float& c2, float& c3,
                                        uint32_t a0, uint32_t a1, uint32_t a2, uint32_t a3,
                                        uint32_t b0, uint32_t b1) {
    asm volatile(
        "mma.sync.aligned.m16n8k16.row.col.f32.f16.f16.f32 "
        "{%0,%1,%2,%3}, {%4,%5,%6,%7}, {%8,%9}, {%0,%1,%2,%3};"
        : "+f"(c0), "+f"(c1), "+f"(c2), "+f"(c3)
        : "r"(a0), "r"(a1), "r"(a2), "r"(a3), "r"(b0), "r"(b1));
}

// SW128 swizzle for 128-byte rows
__device__ __forceinline__ uint32_t sw128(uint32_t off) {
    return off ^ ((off >> 3) & 0x70);
}

// ---------------------------------------------------------------------------
// CSR build: zero counts -> histogram -> scan -> fill
// ---------------------------------------------------------------------------
__global__ void zero_cnt_kernel() {
    int i = blockIdx.x * blockDim.x + threadIdx.x;
    if (i < N_NODES) g_cnt[i] = 0;
}

__global__ void hist_kernel(const int* __restrict__ row, int E) {
    int e = blockIdx.x * blockDim.x + threadIdx.x;
    if (e < E) atomicAdd(&g_cnt[row[e]], 1);
}

// Single-block exclusive scan of g_cnt -> g_ofs; re-init g_cnt as fill cursor.
__global__ __launch_bounds__(1024) void scan_kernel() {
    __shared__ int s[1024];
    const int t = threadIdx.x;
    const int PER = 20;                        // 1024*20 = 20480 >= N_NODES
    const int beg = t * PER;
    const int end = min(beg + PER, N_NODES);

    int part = 0;
    for (int i = beg; i < end; i++) part += g_cnt[i];
    s[t] = part;
    __syncthreads();
    for (int off = 1; off < 1024; off <<= 1) {
        int v = (t >= off) ? s[t - off] : 0;
        __syncthreads();
        s[t] += v;
        __syncthreads();
    }
    int base = s[t] - part;                    // exclusive prefix
    for (int i = beg; i < end; i++) {
        int c = g_cnt[i];
        g_ofs[i] = base;
        g_cnt[i] = base;                       // cursor for fill
        base += c;
    }
    if (t == 1023) g_ofs[N_NODES] = base;      // == E (tail parts are 0)
}

__global__ void fill_kernel(const float* __restrict__ vals,
                            const int* __restrict__ row,
                            const int* __restrict__ col, int E) {
    int e = blockIdx.x * blockDim.x + threadIdx.x;
    if (e < E) {
        int p = atomicAdd(&g_cnt[row[e]], 1);
        g_csr_col[p] = col[e];
        g_csr_val[p] = vals[e];
    }
}

// ---------------------------------------------------------------------------
// Gather (fp32 x, fp32 accum) + fp16 convert of the result row.
// One node per 128 threads (4 nodes / 512-thread block).  [R15 version]
// ---------------------------------------------------------------------------
__global__ __launch_bounds__(512) void gather_split_kernel(const float* __restrict__ x)
{
    const int node = blockIdx.x * 4 + (threadIdx.x >> 7);
    if (node >= N_NODES) return;
    const int f4 = threadIdx.x & 127;

    const int beg = g_ofs[node];
    const int end = g_ofs[node + 1];

    float4 acc = make_float4(0.f, 0.f, 0.f, 0.f);
    for (int p = beg; p < end; p++) {
        const int   c = g_csr_col[p];          // warp-uniform (broadcast)
        const float v = g_csr_val[p];
        float4 xv = reinterpret_cast<const float4*>(x + (size_t)c * N_IN)[f4];
        acc.x += v * xv.x; acc.y += v * xv.y;
        acc.z += v * xv.z; acc.w += v * xv.w;
    }

    __half2 H0 = __halves2half2(__float2half_rn(acc.x), __float2half_rn(acc.y));
    __half2 H1 = __halves2half2(__float2half_rn(acc.z), __float2half_rn(acc.w));
    uint2* hp = reinterpret_cast<uint2*>(g_Ahi + (size_t)node * N_IN) + f4;
    *hp = make_uint2(*reinterpret_cast<uint32_t*>(&H0),
                     *reinterpret_cast<uint32_t*>(&H1));
}

// ---------------------------------------------------------------------------
// W convert to fp16
// ---------------------------------------------------------------------------
__global__ void split_w_kernel(const float* __restrict__ W) {
    const int n4 = (N_OUT * N_IN) / 4;
    uint32_t* hi = reinterpret_cast<uint32_t*>(g_Whi);
    const float4* src = reinterpret_cast<const float4*>(W);
    for (int i = blockIdx.x * blockDim.x + threadIdx.x; i < n4;
         i += gridDim.x * blockDim.x) {
        float4 f = src[i];
        __half2 H0 = __halves2half2(__float2half_rn(f.x), __float2half_rn(f.y));
        __half2 H1 = __halves2half2(__float2half_rn(f.z), __float2half_rn(f.w));
        hi[i * 2]     = *reinterpret_cast<uint32_t*>(&H0);
        hi[i * 2 + 1] = *reinterpret_cast<uint32_t*>(&H1);
    }
}

// ---------------------------------------------------------------------------
// GEMM: out = agg @ W^T via mma.sync fp16, single chain, fp32 accum.
// Block tile 128x128, K=64 stages (2 tiles x 16 KB = 32 KB/stage),
// THREE stages (96 KB) -> 2 CTAs/SM, ONE __syncthreads per K-step.
// ---------------------------------------------------------------------------
#define GBM 128
#define GBN 128
#define NSTEP (N_IN / 64)      // 8 K-steps of 64

#define T_AHI 0
#define T_BHI 16384
#define STAGE_SZ 32768
#define GEMM_SMEM (3 * STAGE_SZ)   // 96 KB

__global__ __launch_bounds__(256, 2) void mma_gemm_kernel(float* __restrict__ out)
{
    extern __shared__ __align__(1024) char smem[];
    const uint32_t sbase = smem_u32(smem);
    const int tid = threadIdx.x;
    const int wid = tid >> 5;
    const int lane = tid & 31;
    const int wm = wid >> 2;            // 0..1 : rows wm*64
    const int wn = wid & 3;             // 0..3 : cols wn*32
    const int m0 = blockIdx.y * GBM;
    const int n0 = blockIdx.x * GBN;

    const int r = tid >> 1;             // 0..127 (tile row this thread loads)
    const int h = tid & 1;              // 0..1   (which 64B half of the 128B row)
    const char* srcA = (const char*)(g_Ahi + (size_t)(m0 + r) * N_IN);
    const char* srcB = (const char*)(g_Whi + (size_t)(n0 + r) * N_IN);

    // Load one K64 step (2 tiles x 128 rows x 128B) into a stage; commit group.
    auto load_step = [&](int step, uint32_t stg) {
        const int cbyte = step * 128;                // 64 fp16 = 128B per row
        #pragma unroll
        for (int jj = 0; jj < 4; jj++) {
            const int j = h * 4 + jj;                // 16B chunk 0..7
            const uint32_t dst = sw128((uint32_t)(r * 128 + j * 16));
            const int so = cbyte + j * 16;
            cp_async16(sbase + stg + T_AHI + dst, srcA + so);
            cp_async16(sbase + stg + T_BHI + dst, srcB + so);
        }
        asm volatile("cp.async.commit_group;" ::: "memory");
    };

    float acc[4][4][4];
    #pragma unroll
    for (int i = 0; i < 4; i++)
        #pragma unroll
        for (int j = 0; j < 4; j++)
            #pragma unroll
            for (int k = 0; k < 4; k++) acc[i][j][k] = 0.f;

    // Prologue: stages 0 and 1 in flight.
    load_step(0, 0);
    load_step(1, STAGE_SZ);

    for (int s = 0; s < NSTEP; s++) {
        const uint32_t stg = (uint32_t)(s % 3) * STAGE_SZ;

        // Wait until at most 1 group pending -> group s complete.
        asm volatile("cp.async.wait_group 1;" ::: "memory");
        __syncthreads();   // data(s) visible; all warps done computing s-1

        if (s + 2 < NSTEP)
            load_step(s + 2, (uint32_t)((s + 2) % 3) * STAGE_SZ);

        #pragma unroll
        for (int ks = 0; ks < 4; ks++) {     // four K16 sub-steps per stage
            uint32_t a[4][4], bh[4][2];

            // A fragments
            #pragma unroll
            for (int mf = 0; mf < 4; mf++) {
                uint32_t off = (uint32_t)((wm * 64 + mf * 16 +
                               ((lane >> 3) & 1) * 8 + (lane & 7)) * 128
                               + ks * 32 + (lane >> 4) * 16);
                ldsm_x4(a[mf][0], a[mf][1], a[mf][2], a[mf][3],
                        sbase + stg + T_AHI + sw128(off));
            }
            // B fragments
            #pragma unroll
            for (int nf2 = 0; nf2 < 2; nf2++) {
                uint32_t off = (uint32_t)((wn * 32 + nf2 * 16 +
                               ((lane >> 4) & 1) * 8 + (lane & 7)) * 128
                               + ks * 32 + ((lane >> 3) & 1) * 16);
                ldsm_x4(bh[nf2 * 2][0], bh[nf2 * 2][1],
                        bh[nf2 * 2 + 1][0], bh[nf2 * 2 + 1][1],
                        sbase + stg + T_BHI + sw128(off));
            }
            #pragma unroll
            for (int mf = 0; mf < 4; mf++)
                #pragma unroll
                for (int nf = 0; nf < 4; nf++)
                    mma_f16(acc[mf][nf][0], acc[mf][nf][1],
                            acc[mf][nf][2], acc[mf][nf][3],
                            a[mf][0], a[mf][1], a[mf][2], a[mf][3],
                            bh[nf][0], bh[nf][1]);
        }
    }

    // ---- epilogue (no smem use; no final sync needed) ----
    #pragma unroll
    for (int mf = 0; mf < 4; mf++) {
        const int mrow = m0 + wm * 64 + mf * 16 + (lane >> 2);
        #pragma unroll
        for (int nf = 0; nf < 4; nf++) {
            const int ncol = n0 + wn * 32 + nf * 8 + (lane & 3) * 2;
            if (mrow < N_NODES) {
                float2* p = reinterpret_cast<float2*>(out + (size_t)mrow * N_OUT + ncol);
                *p = make_float2(acc[mf][nf][0], acc[mf][nf][1]);
            }
            if (mrow + 8 < N_NODES) {
                float2* p = reinterpret_cast<float2*>(out + (size_t)(mrow + 8) * N_OUT + ncol);
                *p = make_float2(acc[mf][nf][2], acc[mf][nf][3]);
            }
        }
    }
}

// ---------------------------------------------------------------------------
// Launch
// ---------------------------------------------------------------------------
extern "C" void kernel_launch(void* const* d_in, const int* in_sizes, int n_in,
                              void* d_out, int out_size)
{
    const float* x    = (const float*)d_in[0];
    const float* vals = (const float*)d_in[1];
    const float* W    = (const float*)d_in[2];
    const int*   row  = (const int*)d_in[3];
    const int*   col  = (const int*)d_in[4];
    float*       out  = (float*)d_out;

    int E = in_sizes[1];

    static bool s_init = false;
    if (!s_init) {
        cudaFuncSetAttribute(mma_gemm_kernel,
                             cudaFuncAttributeMaxDynamicSharedMemorySize, GEMM_SMEM);
        s_init = true;
    }

    zero_cnt_kernel<<<(N_NODES + 511) / 512, 512>>>();
    hist_kernel<<<(E + 511) / 512, 512>>>(row, E);
    scan_kernel<<<1, 1024>>>();
    fill_kernel<<<(E + 511) / 512, 512>>>(vals, row, col, E);
    gather_split_kernel<<<(N_NODES + 3) / 4, 512>>>(x);
    split_w_kernel<<<256, 256>>>(W);

    dim3 grid(N_OUT / GBN, M_PAD / GBM);   // (4, 157)
    mma_gemm_kernel<<<grid, 256, GEMM_SMEM>>>(out);
}